// round 1
// baseline (speedup 1.0000x reference)
#include <cuda_runtime.h>
#include <math.h>

#define BB 4
#define VV 5
#define CC 32
#define HH 256
#define WW 320
#define DD 4
#define GG 8
#define HWSZ (HH * WW)
#define SIM_SIZE (BB * GG * DD * HWSZ)

// rot(9) + trans(3) per (batch, src view)
__device__ float g_rt[BB][VV - 1][12];

// ---------------------------------------------------------------------------
// Projection precompute: P = src_proj_new @ inv(ref_proj_new) per (b, i)
// ---------------------------------------------------------------------------
__device__ void build_projnew(double M[4][4], const float* E, const float* K) {
    for (int r = 0; r < 4; r++)
        for (int c = 0; c < 4; c++)
            M[r][c] = (double)E[r * 4 + c];
    for (int r = 0; r < 3; r++)
        for (int c = 0; c < 4; c++) {
            double s = 0.0;
            for (int k = 0; k < 3; k++)
                s += (double)K[r * 4 + k] * (double)E[k * 4 + c];
            M[r][c] = s;
        }
}

__device__ void inv4(const double A[4][4], double Ai[4][4]) {
    double a[4][8];
    for (int r = 0; r < 4; r++)
        for (int c = 0; c < 4; c++) {
            a[r][c] = A[r][c];
            a[r][4 + c] = (r == c) ? 1.0 : 0.0;
        }
    for (int col = 0; col < 4; col++) {
        int piv = col;
        double best = fabs(a[col][col]);
        for (int r = col + 1; r < 4; r++) {
            double v = fabs(a[r][col]);
            if (v > best) { best = v; piv = r; }
        }
        if (piv != col) {
            for (int c = 0; c < 8; c++) {
                double t = a[col][c]; a[col][c] = a[piv][c]; a[piv][c] = t;
            }
        }
        double d = a[col][col];
        for (int c = 0; c < 8; c++) a[col][c] /= d;
        for (int r = 0; r < 4; r++) {
            if (r == col) continue;
            double f = a[r][col];
            for (int c = 0; c < 8; c++) a[r][c] -= f * a[col][c];
        }
    }
    for (int r = 0; r < 4; r++)
        for (int c = 0; c < 4; c++)
            Ai[r][c] = a[r][4 + c];
}

__global__ void proj_kernel(const float* __restrict__ pm) {
    int t = threadIdx.x;
    if (t >= BB * (VV - 1)) return;
    int b = t / (VV - 1);
    int i = t % (VV - 1) + 1;

    const float* E0 = pm + (((size_t)b * VV + 0) * 2 + 0) * 16;
    const float* K0 = pm + (((size_t)b * VV + 0) * 2 + 1) * 16;
    const float* Ei = pm + (((size_t)b * VV + i) * 2 + 0) * 16;
    const float* Ki = pm + (((size_t)b * VV + i) * 2 + 1) * 16;

    double refN[4][4], srcN[4][4], refInv[4][4];
    build_projnew(refN, E0, K0);
    build_projnew(srcN, Ei, Ki);
    inv4(refN, refInv);

    // P = srcN @ refInv, need rows 0..2
    for (int r = 0; r < 3; r++) {
        double prow[4];
        for (int c = 0; c < 4; c++) {
            double s = 0.0;
            for (int k = 0; k < 4; k++)
                s += srcN[r][k] * refInv[k][c];
            prow[c] = s;
        }
        g_rt[b][i - 1][r * 3 + 0] = (float)prow[0];
        g_rt[b][i - 1][r * 3 + 1] = (float)prow[1];
        g_rt[b][i - 1][r * 3 + 2] = (float)prow[2];
        g_rt[b][i - 1][9 + r]     = (float)prow[3];
    }
}

// ---------------------------------------------------------------------------
// Fused cost-volume kernel: one thread per pixel.
// ---------------------------------------------------------------------------
__global__ void __launch_bounds__(128)
cost_kernel(const float* __restrict__ depth_values,
            const float* __restrict__ features,
            const float* __restrict__ depth_interval,
            const float* __restrict__ view_weights,
            float* __restrict__ out) {
    int pix = blockIdx.x * blockDim.x + threadIdx.x;
    if (pix >= BB * HWSZ) return;
    int x = pix % WW;
    int y = (pix / WW) % HH;
    int b = pix / HWSZ;
    int yx = y * WW + x;

    // Depth samples (inverse-depth range, then invert back)
    float cur = 1.0f / depth_values[pix];
    float itv = depth_interval[pix];
    float dmin = cur - 2.0f * itv;
    float dmax = cur + 2.0f * itv;
    float step = (dmax - dmin) * (1.0f / 3.0f);

    float depths[DD];
#pragma unroll
    for (int d = 0; d < DD; d++) {
        float s = dmin + (float)d * step;
        depths[d] = 1.0f / s;
        out[SIM_SIZE + (((size_t)b * DD + d) * HWSZ) + yx] = depths[d];
    }

    // Preload reference features (coalesced across warp for each channel)
    const float* refp = features + ((size_t)b * VV + 0) * CC * HWSZ + yx;
    float rf[CC];
#pragma unroll
    for (int c = 0; c < CC; c++)
        rf[c] = __ldg(refp + (size_t)c * HWSZ);

    float acc[GG][DD];
#pragma unroll
    for (int g = 0; g < GG; g++)
#pragma unroll
        for (int d = 0; d < DD; d++)
            acc[g][d] = 0.0f;

    float wsum = 0.0f;
    float fx = (float)x, fy = (float)y;

    for (int i = 1; i < VV; i++) {
        float vw = __ldg(view_weights + ((size_t)b * (VV - 1) + (i - 1)) * HWSZ + yx);
        wsum += vw;
        float vw4 = vw * 0.25f;

        const float* rt = g_rt[b][i - 1];
        float r0 = rt[0], r1 = rt[1], r2 = rt[2];
        float r3 = rt[3], r4 = rt[4], r5 = rt[5];
        float r6 = rt[6], r7 = rt[7], r8 = rt[8];
        float t0 = rt[9], t1 = rt[10], t2 = rt[11];

        float rx = r0 * fx + r1 * fy + r2;
        float ry = r3 * fx + r4 * fy + r5;
        float rz = r6 * fx + r7 * fy + r8;

        const float* srcb = features + ((size_t)b * VV + i) * CC * HWSZ;

#pragma unroll
        for (int d = 0; d < DD; d++) {
            float z = depths[d];
            float px = rx * z + t0;
            float py = ry * z + t1;
            float pz = rz * z + t2;
            float iz = 1.0f / pz;
            float gx = px * iz;
            float gy = py * iz;

            float x0f = floorf(gx), y0f = floorf(gy);
            float wx1 = gx - x0f, wy1 = gy - y0f;
            float wx0 = 1.0f - wx1, wy0 = 1.0f - wy1;
            int x0 = (int)x0f, y0 = (int)y0f;
            int x1 = x0 + 1, y1 = y0 + 1;

            float vx0 = (x0 >= 0 && x0 <= WW - 1) ? 1.0f : 0.0f;
            float vx1 = (x1 >= 0 && x1 <= WW - 1) ? 1.0f : 0.0f;
            float vy0 = (y0 >= 0 && y0 <= HH - 1) ? 1.0f : 0.0f;
            float vy1 = (y1 >= 0 && y1 <= HH - 1) ? 1.0f : 0.0f;

            float w00 = wx0 * wy0 * vx0 * vy0;
            float w10 = wx1 * wy0 * vx1 * vy0;
            float w01 = wx0 * wy1 * vx0 * vy1;
            float w11 = wx1 * wy1 * vx1 * vy1;

            int xc0 = min(max(x0, 0), WW - 1);
            int xc1 = min(max(x1, 0), WW - 1);
            int yc0 = min(max(y0, 0), HH - 1);
            int yc1 = min(max(y1, 0), HH - 1);

            int o00 = yc0 * WW + xc0;
            int o10 = yc0 * WW + xc1;
            int o01 = yc1 * WW + xc0;
            int o11 = yc1 * WW + xc1;

#pragma unroll
            for (int g = 0; g < GG; g++) {
                float s = 0.0f;
#pragma unroll
                for (int cc = 0; cc < 4; cc++) {
                    int c = g * 4 + cc;
                    const float* p = srcb + (size_t)c * HWSZ;
                    float wv = w00 * __ldg(p + o00) + w10 * __ldg(p + o10) +
                               w01 * __ldg(p + o01) + w11 * __ldg(p + o11);
                    s += wv * rf[c];
                }
                acc[g][d] += s * vw4;
            }
        }
    }

    float inv_w = 1.0f / (wsum + 1e-6f);
#pragma unroll
    for (int g = 0; g < GG; g++)
#pragma unroll
        for (int d = 0; d < DD; d++) {
            int ch = g * DD + d;
            out[(((size_t)b * (GG * DD) + ch) * HWSZ) + yx] = acc[g][d] * inv_w;
        }
}

// ---------------------------------------------------------------------------
// Launch
// ---------------------------------------------------------------------------
extern "C" void kernel_launch(void* const* d_in, const int* in_sizes, int n_in,
                              void* d_out, int out_size) {
    const float* depth_values   = (const float*)d_in[0];
    const float* features       = (const float*)d_in[1];
    const float* proj_matrices  = (const float*)d_in[2];
    const float* depth_interval = (const float*)d_in[3];
    // d_in[4] depth_max, d_in[5] depth_min : unused by the reference math
    const float* view_weights   = (const float*)d_in[6];
    float* out = (float*)d_out;

    proj_kernel<<<1, 32>>>(proj_matrices);

    int npix = BB * HWSZ;
    int threads = 128;
    int blocks = (npix + threads - 1) / threads;
    cost_kernel<<<blocks, threads>>>(depth_values, features, depth_interval,
                                     view_weights, out);
}

// round 2
// speedup vs baseline: 1.2910x; 1.2910x over previous
#include <cuda_runtime.h>
#include <cuda_fp16.h>
#include <math.h>

#define BB 4
#define VV 5
#define CC 32
#define HH 256
#define WW 320
#define DD 4
#define GG 8
#define HWSZ (HH * WW)
#define SIM_SIZE (BB * GG * DD * HWSZ)
#define NCHUNK 4              // 8 channels per 16B texel
#define NPLANES (BB * (VV - 1) * NCHUNK)

// rot(9) + trans(3) per (batch, src view)
__device__ float g_rt[BB][VV - 1][12];

// fp16 channel-packed src features: [b][v-1][chunk][HWSZ] texels of 8 halves
__device__ uint4 g_hf[(size_t)NPLANES * HWSZ];

// ---------------------------------------------------------------------------
// Projection precompute: P = src_proj_new @ inv(ref_proj_new) per (b, i)
// ---------------------------------------------------------------------------
__device__ void build_projnew(double M[4][4], const float* E, const float* K) {
    for (int r = 0; r < 4; r++)
        for (int c = 0; c < 4; c++)
            M[r][c] = (double)E[r * 4 + c];
    for (int r = 0; r < 3; r++)
        for (int c = 0; c < 4; c++) {
            double s = 0.0;
            for (int k = 0; k < 3; k++)
                s += (double)K[r * 4 + k] * (double)E[k * 4 + c];
            M[r][c] = s;
        }
}

__device__ void inv4(const double A[4][4], double Ai[4][4]) {
    double a[4][8];
    for (int r = 0; r < 4; r++)
        for (int c = 0; c < 4; c++) {
            a[r][c] = A[r][c];
            a[r][4 + c] = (r == c) ? 1.0 : 0.0;
        }
    for (int col = 0; col < 4; col++) {
        int piv = col;
        double best = fabs(a[col][col]);
        for (int r = col + 1; r < 4; r++) {
            double v = fabs(a[r][col]);
            if (v > best) { best = v; piv = r; }
        }
        if (piv != col) {
            for (int c = 0; c < 8; c++) {
                double t = a[col][c]; a[col][c] = a[piv][c]; a[piv][c] = t;
            }
        }
        double d = a[col][col];
        for (int c = 0; c < 8; c++) a[col][c] /= d;
        for (int r = 0; r < 4; r++) {
            if (r == col) continue;
            double f = a[r][col];
            for (int c = 0; c < 8; c++) a[r][c] -= f * a[col][c];
        }
    }
    for (int r = 0; r < 4; r++)
        for (int c = 0; c < 4; c++)
            Ai[r][c] = a[r][4 + c];
}

__global__ void proj_kernel(const float* __restrict__ pm) {
    int t = threadIdx.x;
    if (t >= BB * (VV - 1)) return;
    int b = t / (VV - 1);
    int i = t % (VV - 1) + 1;

    const float* E0 = pm + (((size_t)b * VV + 0) * 2 + 0) * 16;
    const float* K0 = pm + (((size_t)b * VV + 0) * 2 + 1) * 16;
    const float* Ei = pm + (((size_t)b * VV + i) * 2 + 0) * 16;
    const float* Ki = pm + (((size_t)b * VV + i) * 2 + 1) * 16;

    double refN[4][4], srcN[4][4], refInv[4][4];
    build_projnew(refN, E0, K0);
    build_projnew(srcN, Ei, Ki);
    inv4(refN, refInv);

    for (int r = 0; r < 3; r++) {
        double prow[4];
        for (int c = 0; c < 4; c++) {
            double s = 0.0;
            for (int k = 0; k < 4; k++)
                s += srcN[r][k] * refInv[k][c];
            prow[c] = s;
        }
        g_rt[b][i - 1][r * 3 + 0] = (float)prow[0];
        g_rt[b][i - 1][r * 3 + 1] = (float)prow[1];
        g_rt[b][i - 1][r * 3 + 2] = (float)prow[2];
        g_rt[b][i - 1][9 + r]     = (float)prow[3];
    }
}

// ---------------------------------------------------------------------------
// Repack src features fp32 (B,V,C,H,W) -> fp16 channel-last texels (8 ch / 16B)
// ---------------------------------------------------------------------------
__global__ void __launch_bounds__(256)
repack_kernel(const float* __restrict__ features) {
    int idx = blockIdx.x * blockDim.x + threadIdx.x;
    if (idx >= NPLANES * HWSZ) return;
    int o     = idx % HWSZ;
    int chunk = (idx / HWSZ) % NCHUNK;
    int v     = (idx / (HWSZ * NCHUNK)) % (VV - 1);
    int b     =  idx / (HWSZ * NCHUNK * (VV - 1));

    const float* src = features +
        (((size_t)b * VV + (v + 1)) * CC + chunk * 8) * HWSZ + o;

    __half h[8];
#pragma unroll
    for (int k = 0; k < 8; k++)
        h[k] = __float2half(__ldg(src + (size_t)k * HWSZ));

    uint4 q;
    q.x = ((const unsigned int*)h)[0];
    q.y = ((const unsigned int*)h)[1];
    q.z = ((const unsigned int*)h)[2];
    q.w = ((const unsigned int*)h)[3];
    g_hf[idx] = q;
}

// ---------------------------------------------------------------------------
// Fused cost-volume kernel: one thread per pixel.
// ---------------------------------------------------------------------------
__device__ __forceinline__ float hword(unsigned int w, int hi) {
    __half2 h2 = *reinterpret_cast<__half2*>(&w);
    return hi ? __high2float(h2) : __low2float(h2);
}

__global__ void __launch_bounds__(128)
cost_kernel(const float* __restrict__ depth_values,
            const float* __restrict__ features,
            const float* __restrict__ depth_interval,
            const float* __restrict__ view_weights,
            float* __restrict__ out) {
    int pix = blockIdx.x * blockDim.x + threadIdx.x;
    if (pix >= BB * HWSZ) return;
    int x = pix % WW;
    int y = (pix / WW) % HH;
    int b = pix / HWSZ;
    int yx = y * WW + x;

    // Depth samples (inverse-depth range, then invert back)
    float cur = 1.0f / depth_values[pix];
    float itv = depth_interval[pix];
    float dmin = cur - 2.0f * itv;
    float dmax = cur + 2.0f * itv;
    float step = (dmax - dmin) * (1.0f / 3.0f);

    float depths[DD];
#pragma unroll
    for (int d = 0; d < DD; d++) {
        float s = dmin + (float)d * step;
        depths[d] = 1.0f / s;
        out[SIM_SIZE + (((size_t)b * DD + d) * HWSZ) + yx] = depths[d];
    }

    // Preload reference features (coalesced)
    const float* refp = features + ((size_t)b * VV + 0) * CC * HWSZ + yx;
    float rf[CC];
#pragma unroll
    for (int c = 0; c < CC; c++)
        rf[c] = __ldg(refp + (size_t)c * HWSZ);

    float acc[GG][DD];
#pragma unroll
    for (int g = 0; g < GG; g++)
#pragma unroll
        for (int d = 0; d < DD; d++)
            acc[g][d] = 0.0f;

    float wsum = 0.0f;
    float fx = (float)x, fy = (float)y;

    for (int i = 1; i < VV; i++) {
        float vw = __ldg(view_weights + ((size_t)b * (VV - 1) + (i - 1)) * HWSZ + yx);
        wsum += vw;
        float vw4 = vw * 0.25f;

        const float* rt = g_rt[b][i - 1];
        float r0 = rt[0], r1 = rt[1], r2 = rt[2];
        float r3 = rt[3], r4 = rt[4], r5 = rt[5];
        float r6 = rt[6], r7 = rt[7], r8 = rt[8];
        float t0 = rt[9], t1 = rt[10], t2 = rt[11];

        float rx = r0 * fx + r1 * fy + r2;
        float ry = r3 * fx + r4 * fy + r5;
        float rz = r6 * fx + r7 * fy + r8;

        const uint4* vbase = g_hf + (size_t)((b * (VV - 1) + (i - 1)) * NCHUNK) * HWSZ;

#pragma unroll
        for (int d = 0; d < DD; d++) {
            float z = depths[d];
            float px = rx * z + t0;
            float py = ry * z + t1;
            float pz = rz * z + t2;
            float iz = 1.0f / pz;
            float gx = px * iz;
            float gy = py * iz;

            float x0f = floorf(gx), y0f = floorf(gy);
            float wx1 = gx - x0f, wy1 = gy - y0f;
            float wx0 = 1.0f - wx1, wy0 = 1.0f - wy1;
            int x0 = (int)x0f, y0 = (int)y0f;
            int x1 = x0 + 1, y1 = y0 + 1;

            float vx0 = (x0 >= 0 && x0 <= WW - 1) ? 1.0f : 0.0f;
            float vx1 = (x1 >= 0 && x1 <= WW - 1) ? 1.0f : 0.0f;
            float vy0 = (y0 >= 0 && y0 <= HH - 1) ? 1.0f : 0.0f;
            float vy1 = (y1 >= 0 && y1 <= HH - 1) ? 1.0f : 0.0f;

            float w00 = wx0 * wy0 * vx0 * vy0;
            float w10 = wx1 * wy0 * vx1 * vy0;
            float w01 = wx0 * wy1 * vx0 * vy1;
            float w11 = wx1 * wy1 * vx1 * vy1;

            int xc0 = min(max(x0, 0), WW - 1);
            int xc1 = min(max(x1, 0), WW - 1);
            int yc0 = min(max(y0, 0), HH - 1);
            int yc1 = min(max(y1, 0), HH - 1);

            int o00 = yc0 * WW + xc0;
            int o10 = yc0 * WW + xc1;
            int o01 = yc1 * WW + xc0;
            int o11 = yc1 * WW + xc1;

#pragma unroll
            for (int chunk = 0; chunk < NCHUNK; chunk++) {
                const uint4* p = vbase + (size_t)chunk * HWSZ;
                uint4 q00 = __ldg(p + o00);
                uint4 q10 = __ldg(p + o10);
                uint4 q01 = __ldg(p + o01);
                uint4 q11 = __ldg(p + o11);

                const unsigned int* w00p = (const unsigned int*)&q00;
                const unsigned int* w10p = (const unsigned int*)&q10;
                const unsigned int* w01p = (const unsigned int*)&q01;
                const unsigned int* w11p = (const unsigned int*)&q11;

#pragma unroll
                for (int g2 = 0; g2 < 2; g2++) {
                    float s = 0.0f;
#pragma unroll
                    for (int h = 0; h < 4; h++) {
                        int hh = g2 * 4 + h;       // half index within texel (0..7)
                        int word = hh >> 1;
                        int hi   = hh & 1;
                        int c    = chunk * 8 + hh;
                        float v00 = hword(w00p[word], hi);
                        float v10 = hword(w10p[word], hi);
                        float v01 = hword(w01p[word], hi);
                        float v11 = hword(w11p[word], hi);
                        float wv = w00 * v00 + w10 * v10 + w01 * v01 + w11 * v11;
                        s += wv * rf[c];
                    }
                    acc[chunk * 2 + g2][d] += s * vw4;
                }
            }
        }
    }

    float inv_w = 1.0f / (wsum + 1e-6f);
#pragma unroll
    for (int g = 0; g < GG; g++)
#pragma unroll
        for (int d = 0; d < DD; d++) {
            int ch = g * DD + d;
            out[(((size_t)b * (GG * DD) + ch) * HWSZ) + yx] = acc[g][d] * inv_w;
        }
}

// ---------------------------------------------------------------------------
// Launch
// ---------------------------------------------------------------------------
extern "C" void kernel_launch(void* const* d_in, const int* in_sizes, int n_in,
                              void* d_out, int out_size) {
    const float* depth_values   = (const float*)d_in[0];
    const float* features       = (const float*)d_in[1];
    const float* proj_matrices  = (const float*)d_in[2];
    const float* depth_interval = (const float*)d_in[3];
    const float* view_weights   = (const float*)d_in[6];
    float* out = (float*)d_out;

    proj_kernel<<<1, 32>>>(proj_matrices);

    int nrep = NPLANES * HWSZ;
    repack_kernel<<<(nrep + 255) / 256, 256>>>(features);

    int npix = BB * HWSZ;
    int threads = 128;
    int blocks = (npix + threads - 1) / threads;
    cost_kernel<<<blocks, threads>>>(depth_values, features, depth_interval,
                                     view_weights, out);
}

// round 3
// speedup vs baseline: 1.3953x; 1.0808x over previous
#include <cuda_runtime.h>
#include <cuda_fp16.h>
#include <math.h>

#define BB 4
#define VV 5
#define CC 32
#define HH 256
#define WW 320
#define DD 4
#define GG 8
#define HWSZ (HH * WW)
#define SIM_SIZE (BB * GG * DD * HWSZ)
#define NCHUNK 4              // 8 channels per 16B texel
#define NPLANES (BB * (VV - 1) * NCHUNK)

// rot(9) + trans(3) per (batch, src view)
__device__ float g_rt[BB][VV - 1][12];

// fp16 channel-packed src features: [b][v-1][chunk][HWSZ] texels of 8 halves
__device__ uint4 g_hf[(size_t)NPLANES * HWSZ];

// ---------------------------------------------------------------------------
// Projection precompute.  proj_new = [[K3 @ (E rows 0..2)], [0 0 0 1]]
// (extrinsics are rigid -> row 3 is [0,0,0,1]).  So
//   inv(refN) = [[Ainv, -Ainv b], [0, 1]],  A = K3 R_ref (3x3), b = K3 t_ref
//   P = srcN @ inv(refN):  rot = As @ Ainv,  trans = bs - As @ Ainv @ b
// 3x3 inverse by adjugate in fp64 (tiny op count, fully accurate).
// ---------------------------------------------------------------------------
__device__ __forceinline__ void kr3(const float* E, const float* K,
                                    double A[3][3], double bvec[3]) {
    for (int r = 0; r < 3; r++) {
        for (int c = 0; c < 3; c++) {
            double s = 0.0;
            for (int k = 0; k < 3; k++)
                s += (double)K[r * 4 + k] * (double)E[k * 4 + c];
            A[r][c] = s;
        }
        double s = 0.0;
        for (int k = 0; k < 3; k++)
            s += (double)K[r * 4 + k] * (double)E[k * 4 + 3];
        bvec[r] = s;
    }
}

__global__ void proj_kernel(const float* __restrict__ pm) {
    int t = threadIdx.x;
    if (t >= BB * (VV - 1)) return;
    int b = t / (VV - 1);
    int i = t % (VV - 1) + 1;

    const float* E0 = pm + (((size_t)b * VV + 0) * 2 + 0) * 16;
    const float* K0 = pm + (((size_t)b * VV + 0) * 2 + 1) * 16;
    const float* Ei = pm + (((size_t)b * VV + i) * 2 + 0) * 16;
    const float* Ki = pm + (((size_t)b * VV + i) * 2 + 1) * 16;

    double A[3][3], bref[3], As[3][3], bs[3];
    kr3(E0, K0, A, bref);
    kr3(Ei, Ki, As, bs);

    // adjugate inverse of A
    double c00 = A[1][1] * A[2][2] - A[1][2] * A[2][1];
    double c01 = A[1][2] * A[2][0] - A[1][0] * A[2][2];
    double c02 = A[1][0] * A[2][1] - A[1][1] * A[2][0];
    double det = A[0][0] * c00 + A[0][1] * c01 + A[0][2] * c02;
    double id = 1.0 / det;
    double Ai[3][3];
    Ai[0][0] = c00 * id;
    Ai[1][0] = c01 * id;
    Ai[2][0] = c02 * id;
    Ai[0][1] = (A[0][2] * A[2][1] - A[0][1] * A[2][2]) * id;
    Ai[1][1] = (A[0][0] * A[2][2] - A[0][2] * A[2][0]) * id;
    Ai[2][1] = (A[0][1] * A[2][0] - A[0][0] * A[2][1]) * id;
    Ai[0][2] = (A[0][1] * A[1][2] - A[0][2] * A[1][1]) * id;
    Ai[1][2] = (A[0][2] * A[1][0] - A[0][0] * A[1][2]) * id;
    Ai[2][2] = (A[0][0] * A[1][1] - A[0][1] * A[1][0]) * id;

    // u = Ainv @ bref
    double u[3];
    for (int r = 0; r < 3; r++)
        u[r] = Ai[r][0] * bref[0] + Ai[r][1] * bref[1] + Ai[r][2] * bref[2];

    // rot = As @ Ainv ; trans = bs - As @ u
    for (int r = 0; r < 3; r++) {
        for (int c = 0; c < 3; c++) {
            double s = As[r][0] * Ai[0][c] + As[r][1] * Ai[1][c] + As[r][2] * Ai[2][c];
            g_rt[b][i - 1][r * 3 + c] = (float)s;
        }
        double tr = bs[r] - (As[r][0] * u[0] + As[r][1] * u[1] + As[r][2] * u[2]);
        g_rt[b][i - 1][9 + r] = (float)tr;
    }
}

// ---------------------------------------------------------------------------
// Repack src features fp32 (B,V,C,H,W) -> fp16 channel-last texels (8 ch/16B)
// ---------------------------------------------------------------------------
__global__ void __launch_bounds__(256)
repack_kernel(const float* __restrict__ features) {
    int idx = blockIdx.x * blockDim.x + threadIdx.x;
    if (idx >= NPLANES * HWSZ) return;
    int o     = idx % HWSZ;
    int chunk = (idx / HWSZ) % NCHUNK;
    int v     = (idx / (HWSZ * NCHUNK)) % (VV - 1);
    int b     =  idx / (HWSZ * NCHUNK * (VV - 1));

    const float* src = features +
        (((size_t)b * VV + (v + 1)) * CC + chunk * 8) * HWSZ + o;

    __half h[8];
#pragma unroll
    for (int k = 0; k < 8; k++)
        h[k] = __float2half(__ldg(src + (size_t)k * HWSZ));

    uint4 q;
    q.x = ((const unsigned int*)h)[0];
    q.y = ((const unsigned int*)h)[1];
    q.z = ((const unsigned int*)h)[2];
    q.w = ((const unsigned int*)h)[3];
    g_hf[idx] = q;
}

// ---------------------------------------------------------------------------
// Fused cost-volume kernel: one thread per pixel.
// ---------------------------------------------------------------------------
__global__ void __launch_bounds__(128, 5)
cost_kernel(const float* __restrict__ depth_values,
            const float* __restrict__ features,
            const float* __restrict__ depth_interval,
            const float* __restrict__ view_weights,
            float* __restrict__ out) {
    int pix = blockIdx.x * blockDim.x + threadIdx.x;
    if (pix >= BB * HWSZ) return;
    int x = pix % WW;
    int y = (pix / WW) % HH;
    int b = pix / HWSZ;
    int yx = y * WW + x;

    // Depth samples (inverse-depth range, then invert back)
    float cur = 1.0f / depth_values[pix];
    float itv = depth_interval[pix];
    float dmin = cur - 2.0f * itv;
    float dmax = cur + 2.0f * itv;
    float step = (dmax - dmin) * (1.0f / 3.0f);

    float depths[DD];
#pragma unroll
    for (int d = 0; d < DD; d++) {
        float s = dmin + (float)d * step;
        depths[d] = 1.0f / s;
        out[SIM_SIZE + (((size_t)b * DD + d) * HWSZ) + yx] = depths[d];
    }

    // Preload reference features (coalesced)
    const float* refp = features + ((size_t)b * VV + 0) * CC * HWSZ + yx;
    float rf[CC];
#pragma unroll
    for (int c = 0; c < CC; c++)
        rf[c] = __ldg(refp + (size_t)c * HWSZ);

    float acc[GG][DD];
#pragma unroll
    for (int g = 0; g < GG; g++)
#pragma unroll
        for (int d = 0; d < DD; d++)
            acc[g][d] = 0.0f;

    float wsum = 0.0f;
    float fx = (float)x, fy = (float)y;

    for (int i = 1; i < VV; i++) {
        float vw = __ldg(view_weights + ((size_t)b * (VV - 1) + (i - 1)) * HWSZ + yx);
        wsum += vw;
        float vw4 = vw * 0.25f;

        const float* rt = g_rt[b][i - 1];
        float r0 = rt[0], r1 = rt[1], r2 = rt[2];
        float r3 = rt[3], r4 = rt[4], r5 = rt[5];
        float r6 = rt[6], r7 = rt[7], r8 = rt[8];
        float t0 = rt[9], t1 = rt[10], t2 = rt[11];

        float rx = r0 * fx + r1 * fy + r2;
        float ry = r3 * fx + r4 * fy + r5;
        float rz = r6 * fx + r7 * fy + r8;

        const uint4* vbase = g_hf + (size_t)((b * (VV - 1) + (i - 1)) * NCHUNK) * HWSZ;

#pragma unroll
        for (int d = 0; d < DD; d++) {
            float z = depths[d];
            float px = rx * z + t0;
            float py = ry * z + t1;
            float pz = rz * z + t2;
            float iz = 1.0f / pz;
            float gx = px * iz;
            float gy = py * iz;

            float x0f = floorf(gx), y0f = floorf(gy);
            float wx1 = gx - x0f, wy1 = gy - y0f;
            float wx0 = 1.0f - wx1, wy0 = 1.0f - wy1;
            int x0 = (int)x0f, y0 = (int)y0f;
            int x1 = x0 + 1, y1 = y0 + 1;

            float vx0 = (x0 >= 0 && x0 <= WW - 1) ? 1.0f : 0.0f;
            float vx1 = (x1 >= 0 && x1 <= WW - 1) ? 1.0f : 0.0f;
            float vy0 = (y0 >= 0 && y0 <= HH - 1) ? 1.0f : 0.0f;
            float vy1 = (y1 >= 0 && y1 <= HH - 1) ? 1.0f : 0.0f;

            float w00 = wx0 * wy0 * vx0 * vy0;
            float w10 = wx1 * wy0 * vx1 * vy0;
            float w01 = wx0 * wy1 * vx0 * vy1;
            float w11 = wx1 * wy1 * vx1 * vy1;

            __half2 hw00 = __float2half2_rn(w00);
            __half2 hw10 = __float2half2_rn(w10);
            __half2 hw01 = __float2half2_rn(w01);
            __half2 hw11 = __float2half2_rn(w11);

            int xc0 = min(max(x0, 0), WW - 1);
            int xc1 = min(max(x1, 0), WW - 1);
            int yc0 = min(max(y0, 0), HH - 1);
            int yc1 = min(max(y1, 0), HH - 1);

            int o00 = yc0 * WW + xc0;
            int o10 = yc0 * WW + xc1;
            int o01 = yc1 * WW + xc0;
            int o11 = yc1 * WW + xc1;

#pragma unroll
            for (int chunk = 0; chunk < NCHUNK; chunk++) {
                const uint4* p = vbase + (size_t)chunk * HWSZ;
                uint4 q00 = __ldg(p + o00);
                uint4 q10 = __ldg(p + o10);
                uint4 q01 = __ldg(p + o01);
                uint4 q11 = __ldg(p + o11);

                const __half2* a00 = (const __half2*)&q00;
                const __half2* a10 = (const __half2*)&q10;
                const __half2* a01 = (const __half2*)&q01;
                const __half2* a11 = (const __half2*)&q11;

                float s0 = 0.0f, s1 = 0.0f;
#pragma unroll
                for (int w = 0; w < 4; w++) {
                    __half2 wv = __hfma2(hw11, a11[w],
                                 __hfma2(hw01, a01[w],
                                 __hfma2(hw10, a10[w],
                                 __hmul2(hw00, a00[w]))));
                    float2 f = __half22float2(wv);
                    int c = chunk * 8 + 2 * w;
                    if (w < 2) {
                        s0 += f.x * rf[c] + f.y * rf[c + 1];
                    } else {
                        s1 += f.x * rf[c] + f.y * rf[c + 1];
                    }
                }
                acc[chunk * 2 + 0][d] += s0 * vw4;
                acc[chunk * 2 + 1][d] += s1 * vw4;
            }
        }
    }

    float inv_w = 1.0f / (wsum + 1e-6f);
#pragma unroll
    for (int g = 0; g < GG; g++)
#pragma unroll
        for (int d = 0; d < DD; d++) {
            int ch = g * DD + d;
            out[(((size_t)b * (GG * DD) + ch) * HWSZ) + yx] = acc[g][d] * inv_w;
        }
}

// ---------------------------------------------------------------------------
// Launch
// ---------------------------------------------------------------------------
extern "C" void kernel_launch(void* const* d_in, const int* in_sizes, int n_in,
                              void* d_out, int out_size) {
    const float* depth_values   = (const float*)d_in[0];
    const float* features       = (const float*)d_in[1];
    const float* proj_matrices  = (const float*)d_in[2];
    const float* depth_interval = (const float*)d_in[3];
    const float* view_weights   = (const float*)d_in[6];
    float* out = (float*)d_out;

    proj_kernel<<<1, 32>>>(proj_matrices);

    int nrep = NPLANES * HWSZ;
    repack_kernel<<<(nrep + 255) / 256, 256>>>(features);

    int npix = BB * HWSZ;
    int threads = 128;
    int blocks = (npix + threads - 1) / threads;
    cost_kernel<<<blocks, threads>>>(depth_values, features, depth_interval,
                                     view_weights, out);
}